// round 1
// baseline (speedup 1.0000x reference)
#include <cuda_runtime.h>
#include <cstdint>

// Problem constants
#define Bsz  16384
#define Gn   128
#define Sn   64
#define Hn   10
#define PHn  100

// ---------------- scratch (transposed gene_layer [G][B]) ----------------
__device__ float g_GL[(size_t)Gn * Bsz];

// ---------------- f32x2 packed helpers (sm_103a FFMA2) ----------------
__device__ __forceinline__ unsigned long long ffma2(unsigned long long a,
                                                    unsigned long long b,
                                                    unsigned long long c) {
    unsigned long long d;
    asm("fma.rn.f32x2 %0, %1, %2, %3;" : "=l"(d) : "l"(a), "l"(b), "l"(c));
    return d;
}
__device__ __forceinline__ unsigned long long dup2(float x) {
    unsigned long long r;
    asm("mov.b64 %0, {%1, %1};" : "=l"(r) : "f"(x));
    return r;
}
__device__ __forceinline__ void unpack2(unsigned long long v, float& lo, float& hi) {
    asm("mov.b64 {%0, %1}, %2;" : "=f"(lo), "=f"(hi) : "l"(v));
}

// =======================================================================
// Stage 1: per-gene MLP  x[B,G,S] -> gene_layer (stored transposed [G,B])
//   grid = (G, B/BT), block = TH1 threads, each thread computes 2 batch rows
// =======================================================================
#define BT   256          // batch rows per CTA
#define TH1  128          // threads (2 b per thread)
#define XPAD 68           // padded row length (floats): conflict-free LDS.128

#define SMEM1_FLOATS (BT * XPAD + Sn * Hn + 12 + 12)
#define SMEM1_BYTES  (SMEM1_FLOATS * 4)

__global__ void __launch_bounds__(TH1)
stage1_kernel(const float* __restrict__ x,
              const float* __restrict__ W1,
              const float* __restrict__ b1,
              const float* __restrict__ W2,
              const float* __restrict__ b2)
{
    extern __shared__ float sm[];
    float* xs  = sm;                       // [BT][XPAD]
    float* ws  = sm + BT * XPAD;           // [S*H] = 640, 8B aligned
    float* b1s = ws + Sn * Hn;             // 10 (+pad)
    float* w2s = b1s + 12;                 // 10 (+pad)

    const int g   = blockIdx.x;
    const int b0  = blockIdx.y * BT;
    const int tid = threadIdx.x;

    // ---- stage weights into smem ----
    const float* W1g = W1 + (size_t)g * Sn * Hn;
    for (int i = tid; i < Sn * Hn; i += TH1) ws[i] = W1g[i];
    if (tid < Hn) {
        b1s[tid] = b1[g * Hn + tid];
        w2s[tid] = W2[g * Hn + tid];
    }

    // ---- stage x tile: BT rows of 64 floats (256B each), coalesced ----
    const float4* x4 = reinterpret_cast<const float4*>(
        x + ((size_t)b0 * Gn + (size_t)g) * Sn);
    float4* xs4 = reinterpret_cast<float4*>(xs);
    for (int i = tid; i < BT * 16; i += TH1) {
        int r = i >> 4, c = i & 15;
        xs4[r * (XPAD / 4) + c] = x4[(size_t)r * (Gn * 16) + c];
    }
    __syncthreads();

    // ---- compute: 2 batch rows per thread, f32x2 over H pairs ----
    const unsigned long long* wsu =
        reinterpret_cast<const unsigned long long*>(ws);
    const unsigned long long* b1u =
        reinterpret_cast<const unsigned long long*>(b1s);

    unsigned long long accA[5], accB[5];
#pragma unroll
    for (int hp = 0; hp < 5; hp++) { accA[hp] = b1u[hp]; accB[hp] = b1u[hp]; }

    const float4* xrA = reinterpret_cast<const float4*>(xs) + tid * (XPAD / 4);
    const float4* xrB = xrA + TH1 * (XPAD / 4);

#pragma unroll 4
    for (int s4 = 0; s4 < 16; s4++) {
        float4 xa = xrA[s4];
        float4 xb = xrB[s4];
#pragma unroll
        for (int j = 0; j < 4; j++) {
            float fa = (j == 0) ? xa.x : (j == 1) ? xa.y : (j == 2) ? xa.z : xa.w;
            float fb = (j == 0) ? xb.x : (j == 1) ? xb.y : (j == 2) ? xb.z : xb.w;
            unsigned long long a2 = dup2(fa);
            unsigned long long c2 = dup2(fb);
            const int s = s4 * 4 + j;
#pragma unroll
            for (int hp = 0; hp < 5; hp++) {
                unsigned long long w = wsu[s * 5 + hp];   // broadcast LDS.64
                accA[hp] = ffma2(a2, w, accA[hp]);
                accB[hp] = ffma2(c2, w, accB[hp]);
            }
        }
    }

    // ---- epilogue: relu, dot W2, + b2 ; coalesced transposed store ----
    const float b2v = b2[g];
    float glA = b2v, glB = b2v;
#pragma unroll
    for (int hp = 0; hp < 5; hp++) {
        float l, h;
        unpack2(accA[hp], l, h);
        glA += fmaxf(l, 0.f) * w2s[2 * hp] + fmaxf(h, 0.f) * w2s[2 * hp + 1];
        unpack2(accB[hp], l, h);
        glB += fmaxf(l, 0.f) * w2s[2 * hp] + fmaxf(h, 0.f) * w2s[2 * hp + 1];
    }
    g_GL[(size_t)g * Bsz + b0 + tid]        = glA;
    g_GL[(size_t)g * Bsz + b0 + tid + TH1]  = glB;
}

// =======================================================================
// Stage 2: predictor  gene_layer[B,G] -> relu(@Wp1+bp1) @ Wp2 + bp2
//   grid = B/BW CTAs, 128 threads (thread = phenotype-hidden unit)
// =======================================================================
#define TH2  128
#define BW   32            // batch rows per CTA
#define WPAD 132           // padded row (floats), conflict-free LDS.128

#define SMEM2_FLOATS (PHn * WPAD + BW * WPAD + BW * 4)
#define SMEM2_BYTES  (SMEM2_FLOATS * 4)

__global__ void __launch_bounds__(TH2)
stage2_kernel(const float* __restrict__ Wp1,
              const float* __restrict__ bp1,
              const float* __restrict__ Wp2,
              const float* __restrict__ bp2,
              float* __restrict__ out)
{
    extern __shared__ float sm[];
    float* wp      = sm;                      // [PH][WPAD]  (transposed Wp1)
    float* gls     = sm + PHn * WPAD;         // [BW][WPAD]  (gene_layer rows)
    float* partial = gls + BW * WPAD;         // [BW][4]

    const int tid = threadIdx.x;
    const int b0  = blockIdx.x * BW;

    // Wp1 [G,PH] -> smem transposed [ph][g]
    for (int i = tid; i < Gn * PHn; i += TH2) {
        int gg = i / PHn, ph = i % PHn;
        wp[ph * WPAD + gg] = Wp1[i];          // coalesced gmem read
    }
    // gene_layer tile: gls[bi][g] = g_GL[g][b0+bi]   (coalesced 128B per g)
    for (int i = tid; i < Gn * BW; i += TH2) {
        int gg = i >> 5, bi = i & 31;
        gls[bi * WPAD + gg] = g_GL[(size_t)gg * Bsz + b0 + bi];
    }
    __syncthreads();

    const float bp1v = (tid < PHn) ? bp1[tid] : 0.f;
    const float wp2v = (tid < PHn) ? Wp2[tid] : 0.f;
    const int lane = tid & 31, wrp = tid >> 5;

    const float4* wpr = reinterpret_cast<const float4*>(wp + tid * WPAD);

    for (int bi = 0; bi < BW; bi++) {
        const float4* glr = reinterpret_cast<const float4*>(gls + bi * WPAD);
        float acc = bp1v;
#pragma unroll
        for (int q = 0; q < 32; q++) {
            float4 g4 = glr[q];               // broadcast
            float4 w4 = wpr[q];               // conflict-free (WPAD pad)
            acc = fmaf(g4.x, w4.x, acc);
            acc = fmaf(g4.y, w4.y, acc);
            acc = fmaf(g4.z, w4.z, acc);
            acc = fmaf(g4.w, w4.w, acc);
        }
        float y = (tid < PHn) ? fmaxf(acc, 0.f) * wp2v : 0.f;
#pragma unroll
        for (int off = 16; off > 0; off >>= 1)
            y += __shfl_down_sync(0xffffffffu, y, off);
        if (lane == 0) partial[bi * 4 + wrp] = y;
    }
    __syncthreads();
    if (tid < BW) {
        float r = partial[tid * 4 + 0] + partial[tid * 4 + 1] +
                  partial[tid * 4 + 2] + partial[tid * 4 + 3] + bp2[0];
        out[b0 + tid] = r;
    }
}

// =======================================================================
extern "C" void kernel_launch(void* const* d_in, const int* in_sizes, int n_in,
                              void* d_out, int out_size)
{
    const float* x   = (const float*)d_in[0];
    const float* W1  = (const float*)d_in[1];
    const float* b1  = (const float*)d_in[2];
    const float* W2  = (const float*)d_in[3];
    const float* b2  = (const float*)d_in[4];
    const float* Wp1 = (const float*)d_in[5];
    const float* bp1 = (const float*)d_in[6];
    const float* Wp2 = (const float*)d_in[7];
    const float* bp2 = (const float*)d_in[8];
    float* out = (float*)d_out;

    cudaFuncSetAttribute(stage1_kernel,
                         cudaFuncAttributeMaxDynamicSharedMemorySize, SMEM1_BYTES);
    cudaFuncSetAttribute(stage2_kernel,
                         cudaFuncAttributeMaxDynamicSharedMemorySize, SMEM2_BYTES);

    dim3 grid1(Gn, Bsz / BT);
    stage1_kernel<<<grid1, TH1, SMEM1_BYTES>>>(x, W1, b1, W2, b2);
    stage2_kernel<<<Bsz / BW, TH2, SMEM2_BYTES>>>(Wp1, bp1, Wp2, bp2, out);
}

// round 2
// speedup vs baseline: 1.2393x; 1.2393x over previous
#include <cuda_runtime.h>
#include <cstdint>

#define Bsz  16384
#define Gn   128
#define Sn   64
#define Hn   10
#define PHn  100

typedef unsigned long long ull;

// scratch: gene_layer stored transposed [G][B]
__device__ float g_GL[(size_t)Gn * Bsz];

// ---------------- packed f32x2 helpers (sm_103a) ----------------
__device__ __forceinline__ ull ffma2(ull a, ull b, ull c) {
    ull d;
    asm("fma.rn.f32x2 %0, %1, %2, %3;" : "=l"(d) : "l"(a), "l"(b), "l"(c));
    return d;
}
__device__ __forceinline__ ull add2(ull a, ull b) {
    ull d;
    asm("add.rn.f32x2 %0, %1, %2;" : "=l"(d) : "l"(a), "l"(b));
    return d;
}
__device__ __forceinline__ ull dup2(float x) {
    ull r;
    asm("mov.b64 %0, {%1, %1};" : "=l"(r) : "f"(x));
    return r;
}
__device__ __forceinline__ void unpack2(ull v, float& lo, float& hi) {
    asm("mov.b64 {%0, %1}, %2;" : "=f"(lo), "=f"(hi) : "l"(v));
}

// =======================================================================
// Stage 1: per-gene MLP, direct coalesced LDG of x, W1 broadcast from smem
//   4 lanes per batch row (16 interleaved SNPs each), 2 rows per thread.
//   grid = (G, B/ROWS1), block = 256
// =======================================================================
#define TH1     256
#define ROWS1   512            // rows per CTA
#define PASS1   (ROWS1 / 128)  // 8 warps * 16 rows per pass

// smem: W1 pairs slice-major [4][82] u64 (padded, bank-conflict free) + b1 pairs
__global__ void __launch_bounds__(TH1)
stage1_kernel(const float* __restrict__ x,
              const float* __restrict__ W1,
              const float* __restrict__ b1,
              const float* __restrict__ W2,
              const float* __restrict__ b2)
{
    __shared__ ull  ws[4 * 82 + 8];     // [slice][ (k*4+i)*5 + hp ]
    __shared__ float w2s[10];
    __shared__ float b2s;

    const int g   = blockIdx.x;
    const int tid = threadIdx.x;

    // ---- stage W1 pairs into padded slice-major smem ----
    const ull* W1u = reinterpret_cast<const ull*>(W1 + (size_t)g * Sn * Hn);
    for (int p = tid; p < Sn * (Hn / 2); p += TH1) {   // 320 pairs
        int s = p / 5, hp = p % 5;
        int j = (s >> 2) & 3;        // slice owner (lane&3)
        int k = s >> 4;              // which 16-s block
        int i = s & 3;               // within 4-run
        ws[j * 82 + (k * 4 + i) * 5 + hp] = W1u[p];
    }
    if (tid < 5)  ws[4 * 82 + tid] = reinterpret_cast<const ull*>(b1 + g * Hn)[tid];
    if (tid < 10) w2s[tid] = W2[g * Hn + tid];
    if (tid == 0) b2s = b2[g];
    __syncthreads();

    const int w    = tid >> 5;
    const int lane = tid & 31;
    const int rg   = lane >> 2;      // row-group within warp (0..7)
    const int j2   = lane & 3;       // slice within row
    const ull* wsl = ws + j2 * 82;

    // hoist small constants to registers
    ull b1r[5];
#pragma unroll
    for (int hp = 0; hp < 5; hp++) b1r[hp] = ws[4 * 82 + hp];
    float w2r[10];
#pragma unroll
    for (int h = 0; h < 10; h++) w2r[h] = w2s[h];
    const float b2v = b2s;

#pragma unroll 1
    for (int pass = 0; pass < PASS1; pass++) {
        const int rA = blockIdx.y * ROWS1 + pass * 128 + w * 16 + rg;
        const int rB = rA + 8;

        const float4* xA = reinterpret_cast<const float4*>(
            x + ((size_t)rA * Gn + g) * Sn);
        const float4* xB = reinterpret_cast<const float4*>(
            x + ((size_t)rB * Gn + g) * Sn);

        // 8 independent coalesced loads (8 rows x 64B contiguous per warp instr)
        float4 xa[4], xb[4];
#pragma unroll
        for (int k = 0; k < 4; k++) {
            xa[k] = xA[k * 4 + j2];
            xb[k] = xB[k * 4 + j2];
        }

        ull accA[5], accB[5];
#pragma unroll
        for (int hp = 0; hp < 5; hp++) { accA[hp] = 0ull; accB[hp] = 0ull; }

#pragma unroll
        for (int k = 0; k < 4; k++) {
            float fa[4] = {xa[k].x, xa[k].y, xa[k].z, xa[k].w};
            float fb[4] = {xb[k].x, xb[k].y, xb[k].z, xb[k].w};
#pragma unroll
            for (int i = 0; i < 4; i++) {
                ull a2 = dup2(fa[i]);
                ull c2 = dup2(fb[i]);
                const ull* wrow = wsl + (k * 4 + i) * 5;
#pragma unroll
                for (int hp = 0; hp < 5; hp++) {
                    ull wv = wrow[hp];                 // broadcast x4 (distinct banks)
                    accA[hp] = ffma2(a2, wv, accA[hp]);
                    accB[hp] = ffma2(c2, wv, accB[hp]);
                }
            }
        }

        // reduce the 4 slice-lanes (butterfly keeps all lanes valid)
#pragma unroll
        for (int off = 1; off <= 2; off <<= 1) {
#pragma unroll
            for (int hp = 0; hp < 5; hp++) {
                accA[hp] = add2(accA[hp], __shfl_xor_sync(0xffffffffu, accA[hp], off));
                accB[hp] = add2(accB[hp], __shfl_xor_sync(0xffffffffu, accB[hp], off));
            }
        }

        // epilogue: +b1, relu, dot W2, +b2
        float glA = b2v, glB = b2v;
#pragma unroll
        for (int hp = 0; hp < 5; hp++) {
            float l, h;
            unpack2(add2(accA[hp], b1r[hp]), l, h);
            glA += fmaxf(l, 0.f) * w2r[2 * hp] + fmaxf(h, 0.f) * w2r[2 * hp + 1];
            unpack2(add2(accB[hp], b1r[hp]), l, h);
            glB += fmaxf(l, 0.f) * w2r[2 * hp] + fmaxf(h, 0.f) * w2r[2 * hp + 1];
        }
        if (j2 == 0) {
            g_GL[(size_t)g * Bsz + rA] = glA;
            g_GL[(size_t)g * Bsz + rB] = glB;
        }
    }
}

// =======================================================================
// Stage 2: thread-per-batch-row, 50 f32x2 register accumulators over PH
//   grid = B/128 CTAs (one wave), block = 128
// =======================================================================
#define TH2  128
#define SMEM2_BYTES (Gn * PHn * 4)   // 51.2 KB

__global__ void __launch_bounds__(TH2)
stage2_kernel(const float* __restrict__ Wp1,
              const float* __restrict__ bp1,
              const float* __restrict__ Wp2,
              const float* __restrict__ bp2,
              float* __restrict__ out)
{
    extern __shared__ float wp[];    // Wp1 [G][PH], rows 400B (16B aligned)
    const int tid = threadIdx.x;
    const int b   = blockIdx.x * TH2 + tid;

    const float4* W4  = reinterpret_cast<const float4*>(Wp1);
    float4*       wp4 = reinterpret_cast<float4*>(wp);
    for (int i = tid; i < Gn * PHn / 4; i += TH2) wp4[i] = W4[i];
    __syncthreads();

    ull acc[50];
    const ull* bp1u = reinterpret_cast<const ull*>(bp1);
#pragma unroll
    for (int p = 0; p < 50; p++) acc[p] = bp1u[p];

    const float* glp = g_GL + b;
#pragma unroll 2
    for (int gg = 0; gg < Gn; gg++) {
        float xv = glp[(size_t)gg * Bsz];            // coalesced
        ull a2 = dup2(xv);
        const ulonglong2* wr =
            reinterpret_cast<const ulonglong2*>(wp + gg * PHn);
#pragma unroll
        for (int q = 0; q < 25; q++) {
            ulonglong2 wv = wr[q];                   // broadcast LDS.128
            acc[2 * q]     = ffma2(a2, wv.x, acc[2 * q]);
            acc[2 * q + 1] = ffma2(a2, wv.y, acc[2 * q + 1]);
        }
    }

    // epilogue: relu, dot Wp2, + bp2
    float y = bp2[0];
    const ull* wp2u = reinterpret_cast<const ull*>(Wp2);
#pragma unroll
    for (int p = 0; p < 50; p++) {
        float l, h, wl, wh;
        unpack2(acc[p], l, h);
        unpack2(wp2u[p], wl, wh);
        y += fmaxf(l, 0.f) * wl + fmaxf(h, 0.f) * wh;
    }
    out[b] = y;
}

// =======================================================================
extern "C" void kernel_launch(void* const* d_in, const int* in_sizes, int n_in,
                              void* d_out, int out_size)
{
    const float* x   = (const float*)d_in[0];
    const float* W1  = (const float*)d_in[1];
    const float* b1  = (const float*)d_in[2];
    const float* W2  = (const float*)d_in[3];
    const float* b2  = (const float*)d_in[4];
    const float* Wp1 = (const float*)d_in[5];
    const float* bp1 = (const float*)d_in[6];
    const float* Wp2 = (const float*)d_in[7];
    const float* bp2 = (const float*)d_in[8];
    float* out = (float*)d_out;

    cudaFuncSetAttribute(stage2_kernel,
                         cudaFuncAttributeMaxDynamicSharedMemorySize, SMEM2_BYTES);

    dim3 grid1(Gn, Bsz / ROWS1);
    stage1_kernel<<<grid1, TH1>>>(x, W1, b1, W2, b2);
    stage2_kernel<<<Bsz / TH2, TH2, SMEM2_BYTES>>>(Wp1, bp1, Wp2, bp2, out);
}

// round 7
// speedup vs baseline: 1.4329x; 1.1562x over previous
#include <cuda_runtime.h>
#include <cstdint>

#define Bsz  16384
#define Gn   128
#define Sn   64
#define Hn   10
#define PHn  100

typedef unsigned long long ull;

// scratch: gene_layer stored transposed [G][B]
__device__ float g_GL[(size_t)Gn * Bsz];

// ---------------- packed f32x2 helpers (sm_103a) ----------------
__device__ __forceinline__ ull ffma2(ull a, ull b, ull c) {
    ull d;
    asm("fma.rn.f32x2 %0, %1, %2, %3;" : "=l"(d) : "l"(a), "l"(b), "l"(c));
    return d;
}
__device__ __forceinline__ ull add2(ull a, ull b) {
    ull d;
    asm("add.rn.f32x2 %0, %1, %2;" : "=l"(d) : "l"(a), "l"(b));
    return d;
}
__device__ __forceinline__ ull dup2(float x) {
    ull r;
    asm("mov.b64 %0, {%1, %1};" : "=l"(r) : "f"(x));
    return r;
}
__device__ __forceinline__ void unpack2(ull v, float& lo, float& hi) {
    asm("mov.b64 {%0, %1}, %2;" : "=f"(lo), "=f"(hi) : "l"(v));
}

// =======================================================================
// Stage 1: per-gene MLP.  4 lanes per row (16 SNPs each), 2 rows/thread,
//   software-pipelined x loads across 8 passes.
//   grid = (G, B/ROWS1), block = 128
// =======================================================================
#define TH1     128
#define ROWS1   512
#define PASS1   8          // 4 warps * 16 rows per pass = 64 rows/pass

__global__ void __launch_bounds__(TH1)
stage1_kernel(const float* __restrict__ x,
              const float* __restrict__ W1,
              const float* __restrict__ b1,
              const float* __restrict__ W2,
              const float* __restrict__ b2)
{
    __shared__ ull  ws[4 * 82 + 8];     // slice-major W1 pairs (padded)
    __shared__ float w2s[10];
    __shared__ float b2s;

    const int g   = blockIdx.x;
    const int tid = threadIdx.x;

    const ull* W1u = reinterpret_cast<const ull*>(W1 + (size_t)g * Sn * Hn);
    for (int p = tid; p < Sn * (Hn / 2); p += TH1) {   // 320 pairs
        int s = p / 5, hp = p % 5;
        int j = (s >> 2) & 3;
        int k = s >> 4;
        int i = s & 3;
        ws[j * 82 + (k * 4 + i) * 5 + hp] = W1u[p];
    }
    if (tid < 5)  ws[4 * 82 + tid] = reinterpret_cast<const ull*>(b1 + g * Hn)[tid];
    if (tid < 10) w2s[tid] = W2[g * Hn + tid];
    if (tid == 0) b2s = b2[g];
    __syncthreads();

    const int w    = tid >> 5;
    const int lane = tid & 31;
    const int rg   = lane >> 2;      // 0..7
    const int j2   = lane & 3;       // slice
    const ull* wsl = ws + j2 * 82;

    ull b1r[5];
#pragma unroll
    for (int hp = 0; hp < 5; hp++) b1r[hp] = ws[4 * 82 + hp];
    float w2r[10];
#pragma unroll
    for (int h = 0; h < 10; h++) w2r[h] = w2s[h];
    const float b2v = b2s;

    const int rowbase = blockIdx.y * ROWS1 + w * 16 + rg;
    const float4* x4 = reinterpret_cast<const float4*>(x);
    // float4 index of (row r, gene g, chunk k, slice j2):
    //   r*2048 + g*16 + k*4 + j2

    float4 ca[4], cb[4];
    {
        const size_t iA = (size_t)rowbase * 2048 + (size_t)g * 16 + j2;
#pragma unroll
        for (int k = 0; k < 4; k++) {
            ca[k] = x4[iA + k * 4];
            cb[k] = x4[iA + 8 * 2048 + k * 4];
        }
    }

#pragma unroll 1
    for (int pass = 0; pass < PASS1; pass++) {
        // ---- prefetch next pass ----
        float4 na[4], nb[4];
        if (pass + 1 < PASS1) {
            const size_t iN = (size_t)(rowbase + (pass + 1) * 64) * 2048
                              + (size_t)g * 16 + j2;
#pragma unroll
            for (int k = 0; k < 4; k++) {
                na[k] = x4[iN + k * 4];
                nb[k] = x4[iN + 8 * 2048 + k * 4];
            }
        }

        // ---- compute current pass ----
        ull accA[5], accB[5];
#pragma unroll
        for (int hp = 0; hp < 5; hp++) { accA[hp] = 0ull; accB[hp] = 0ull; }

#pragma unroll
        for (int k = 0; k < 4; k++) {
            float fa[4] = {ca[k].x, ca[k].y, ca[k].z, ca[k].w};
            float fb[4] = {cb[k].x, cb[k].y, cb[k].z, cb[k].w};
#pragma unroll
            for (int i = 0; i < 4; i++) {
                ull a2 = dup2(fa[i]);
                ull c2 = dup2(fb[i]);
                const ull* wrow = wsl + (k * 4 + i) * 5;
#pragma unroll
                for (int hp = 0; hp < 5; hp++) {
                    ull wv = wrow[hp];
                    accA[hp] = ffma2(a2, wv, accA[hp]);
                    accB[hp] = ffma2(c2, wv, accB[hp]);
                }
            }
        }

#pragma unroll
        for (int off = 1; off <= 2; off <<= 1) {
#pragma unroll
            for (int hp = 0; hp < 5; hp++) {
                accA[hp] = add2(accA[hp], __shfl_xor_sync(0xffffffffu, accA[hp], off));
                accB[hp] = add2(accB[hp], __shfl_xor_sync(0xffffffffu, accB[hp], off));
            }
        }

        float glA = b2v, glB = b2v;
#pragma unroll
        for (int hp = 0; hp < 5; hp++) {
            float l, h;
            unpack2(add2(accA[hp], b1r[hp]), l, h);
            glA += fmaxf(l, 0.f) * w2r[2 * hp] + fmaxf(h, 0.f) * w2r[2 * hp + 1];
            unpack2(add2(accB[hp], b1r[hp]), l, h);
            glB += fmaxf(l, 0.f) * w2r[2 * hp] + fmaxf(h, 0.f) * w2r[2 * hp + 1];
        }
        const int rA = rowbase + pass * 64;
        if (j2 == 0) {
            g_GL[(size_t)g * Bsz + rA]     = glA;
            g_GL[(size_t)g * Bsz + rA + 8] = glB;
        }

#pragma unroll
        for (int k = 0; k < 4; k++) { ca[k] = na[k]; cb[k] = nb[k]; }
    }
}

// =======================================================================
// Stage 2: 4 threads per batch row: (PH half) x (G half).
//   lane layout: bits[0:3)=row(8), bit3=ph half, bit4=g half.
//   grid = B/32 = 512 CTAs, block = 128 (32 rows/CTA)
// =======================================================================
#define TH2   128
#define WROW  104          // padded Wp1 row stride (floats); half1 at +52
#define SMEM2_BYTES (Gn * WROW * 4)   // 53248

__global__ void __launch_bounds__(TH2)
stage2_kernel(const float* __restrict__ Wp1,
              const float* __restrict__ bp1,
              const float* __restrict__ Wp2,
              const float* __restrict__ bp2,
              float* __restrict__ out)
{
    extern __shared__ float wp[];   // [G][WROW]: cols 0..49 = half0, 52..101 = half1
    const int tid  = threadIdx.x;
    const int lane = tid & 31;
    const int wrp  = tid >> 5;

    for (int i = tid; i < Gn * PHn; i += TH2) {
        int gg = i / PHn, p = i % PHn;
        int col = (p < 50) ? p : p + 2;
        wp[gg * WROW + col] = Wp1[i];
    }
    __syncthreads();

    const int row = (lane & 7);
    const int ph  = (lane >> 3) & 1;
    const int gh  = lane >> 4;
    const int b   = blockIdx.x * 32 + wrp * 8 + row;

    ull acc[25];
    if (gh == 0) {
        const ull* bp1u = reinterpret_cast<const ull*>(bp1 + ph * 50);
#pragma unroll
        for (int q = 0; q < 25; q++) acc[q] = bp1u[q];
    } else {
#pragma unroll
        for (int q = 0; q < 25; q++) acc[q] = 0ull;
    }

    const float* glcol = g_GL + (size_t)(gh * 64) * Bsz + b;
    const float* wbase = wp + (gh * 64) * WROW + ph * 52;

#pragma unroll 1
    for (int c = 0; c < 64; c += 8) {
        float gv[8];
#pragma unroll
        for (int j = 0; j < 8; j++) gv[j] = glcol[(size_t)(c + j) * Bsz];
#pragma unroll
        for (int j = 0; j < 8; j++) {
            ull a2 = dup2(gv[j]);
            const float* wr = wbase + (c + j) * WROW;
            const ulonglong2* w2p = reinterpret_cast<const ulonglong2*>(wr);
#pragma unroll
            for (int q = 0; q < 12; q++) {
                ulonglong2 wv = w2p[q];
                acc[2 * q]     = ffma2(a2, wv.x, acc[2 * q]);
                acc[2 * q + 1] = ffma2(a2, wv.y, acc[2 * q + 1]);
            }
            acc[24] = ffma2(a2, reinterpret_cast<const ull*>(wr)[24], acc[24]);
        }
    }

    // combine G halves (lanes xor 16)
#pragma unroll
    for (int q = 0; q < 25; q++)
        acc[q] = add2(acc[q], __shfl_xor_sync(0xffffffffu, acc[q], 16));

    // relu + dot with own Wp2 half
    float y = 0.f;
    const ull* wp2u = reinterpret_cast<const ull*>(Wp2 + ph * 50);
#pragma unroll
    for (int q = 0; q < 25; q++) {
        float l, h, wl, wh;
        unpack2(acc[q], l, h);
        unpack2(wp2u[q], wl, wh);
        y += fmaxf(l, 0.f) * wl + fmaxf(h, 0.f) * wh;
    }
    // combine PH halves (lanes xor 8)
    y += __shfl_xor_sync(0xffffffffu, y, 8);

    if ((lane >> 3) == 0) out[b] = y + bp2[0];
}

// =======================================================================
extern "C" void kernel_launch(void* const* d_in, const int* in_sizes, int n_in,
                              void* d_out, int out_size)
{
    const float* x   = (const float*)d_in[0];
    const float* W1  = (const float*)d_in[1];
    const float* b1  = (const float*)d_in[2];
    const float* W2  = (const float*)d_in[3];
    const float* b2  = (const float*)d_in[4];
    const float* Wp1 = (const float*)d_in[5];
    const float* bp1 = (const float*)d_in[6];
    const float* Wp2 = (const float*)d_in[7];
    const float* bp2 = (const float*)d_in[8];
    float* out = (float*)d_out;

    cudaFuncSetAttribute(stage2_kernel,
                         cudaFuncAttributeMaxDynamicSharedMemorySize, SMEM2_BYTES);

    dim3 grid1(Gn, Bsz / ROWS1);
    stage1_kernel<<<grid1, TH1>>>(x, W1, b1, W2, b2);
    stage2_kernel<<<Bsz / 32, TH2, SMEM2_BYTES>>>(Wp1, bp1, Wp2, bp2, out);
}